// round 8
// baseline (speedup 1.0000x reference)
#include <cuda_runtime.h>
#include <math.h>

#define Bn 2
#define C 32
#define H 256
#define W 512
#define LH 64
#define LW 128

#define STR 36   // row stride (floats): 144B = 16B-aligned rows, bank-rotates by 4

// dynamic shared layout (floats)
#define OFF_W0HR 0            // 1024
#define OFF_W1   1024         // 512
#define OFF_W2   1536         // 128
#define OFF_W3   1664         // 16
#define OFF_X    1680         // 32*128 = 4096
#define OFF_HP   5776         // 128*36 = 4608
#define OFF_P    10384        // 102*36 = 3672
#define OFF_DT   14056        // 36*36  = 1296
#define OFF_L    15352        // 9*128  = 1152
#define SMEM_FLOATS 16504     // 66016 bytes

// Precomputed lr projection: P[b][ly][lx][o] = W0_lr @ lr   (2 MB scratch)
__device__ float g_P[Bn * LH * LW * 32];

// ---------------------------------------------------------------------------
// Kernel 1: P[b,ly,lx,o] = sum_c w0[o,c] * lr[b,c,ly,lx]
// ---------------------------------------------------------------------------
__global__ __launch_bounds__(256) void k_precompute_P(
    const float* __restrict__ lr, const float* __restrict__ w0)
{
    __shared__ float sw[32 * 32];  // [c][o]
    int t = threadIdx.x;
    for (int i = t; i < 32 * 32; i += 256) {
        int c = i >> 5, o = i & 31;
        sw[i] = w0[o * 66 + c];
    }
    __syncthreads();

    int gid = blockIdx.x * 256 + t;
    int pix = gid >> 2;
    int og  = (gid & 3) * 8;
    if (pix >= Bn * LH * LW) return;
    int b   = pix / (LH * LW);
    int rem = pix - b * (LH * LW);

    const float* lp = lr + (size_t)b * C * LH * LW + rem;
    float acc[8];
#pragma unroll
    for (int o = 0; o < 8; o++) acc[o] = 0.f;
#pragma unroll
    for (int c = 0; c < 32; c++) {
        float v = lp[c * (LH * LW)];
#pragma unroll
        for (int o = 0; o < 8; o++)
            acc[o] = fmaf(v, sw[c * 32 + og + o], acc[o]);
    }
    float* P = g_P + (size_t)pix * 32 + og;
#pragma unroll
    for (int o = 0; o < 8; o++) P[o] = acc[o];
}

// ---------------------------------------------------------------------------
// Main kernel. Block = 128-pixel strip (one row) x 9 directions.
// 288 threads = 9 warps; warp k owns direction k; lane handles pixels
// lane, lane+32, lane+64, lane+96 (same px phase -> one dt row for all 4).
// ---------------------------------------------------------------------------
__global__ __launch_bounds__(288, 2) void k_main(
    const float* __restrict__ hr,
    const float* __restrict__ w0,
    const float* __restrict__ w1,
    const float* __restrict__ w2,
    const float* __restrict__ w3,
    float* __restrict__ out)
{
    extern __shared__ float smem[];
    float* sW0hr = smem + OFF_W0HR;   // [c][o]
    float* sW1   = smem + OFF_W1;     // [c][j]
    float* sW2   = smem + OFF_W2;     // [c][j]
    float* sW3   = smem + OFF_W3;
    float* sX    = smem + OFF_X;      // hr tile [c][pix]
    float* sHP   = smem + OFF_HP;     // hpart [pix][o]
    float* sP    = smem + OFF_P;      // P halo [3 x 34 cells][o]
    float* sDT   = smem + OFF_DT;     // dt [k*4+px][o]
    float* sL    = smem + OFF_L;      // logits [k][pix]

    const int tid = threadIdx.x;
    const int x0  = blockIdx.x * 128;
    const int y   = blockIdx.y;
    const int b   = blockIdx.z;
    const int py  = y & 3;
    const int ly0 = y >> 2;
    const int lx0 = x0 >> 2;

    // ---- phase 1: stage weights, hr tile, build dt ----
    for (int i = tid; i < 32 * 32; i += 288) {
        int c = i >> 5, o = i & 31;
        sW0hr[i] = w0[o * 66 + 32 + c];
    }
    for (int i = tid; i < 32 * 16; i += 288) {
        int c = i >> 4, j = i & 15;
        sW1[i] = w1[j * 32 + c];
    }
    for (int i = tid; i < 16 * 8; i += 288) {
        int c = i >> 3, j = i & 7;
        sW2[i] = w2[j * 16 + c];
    }
    if (tid < 8) sW3[tid] = w3[tid];

    for (int i = tid; i < 32 * 128; i += 288) {
        int c = i >> 7, p = i & 127;
        sX[i] = hr[(((size_t)b * C + c) * H + y) * W + x0 + p];
    }

    {
        float byf = (py < 2) ? (float)(py - 2) : (float)(py - 1);
        for (int i = tid; i < 9 * 4 * 32; i += 288) {
            int o  = i & 31;
            int px = (i >> 5) & 3;
            int k  = i >> 7;
            float bxf = (px < 2) ? (float)(px - 2) : (float)(px - 1);
            float d0, d1;
            if (k == 0)                { d0 = bxf;              d1 = byf;              }
            else if (k == 1 || k == 5) { d0 = 4.f - (float)px;  d1 = byf;              }
            else if (k == 2 || k == 6) { d0 = (float)px + 1.f;  d1 = byf;              }
            else if (k == 3 || k == 7) { d0 = bxf;              d1 = 4.f - (float)py;  }
            else                       { d0 = bxf;              d1 = (float)py + 1.f;  }
            sDT[(k * 4 + px) * STR + o] =
                w0[o * 66 + 64] * d0 + w0[o * 66 + 65] * d1;
        }
    }
    __syncthreads();

    // ---- phase 2: hpart from sX; P halo from g_P ----
    for (int i = tid; i < 1024; i += 288) {
        int pix = i & 127;
        int og  = (i >> 7) << 2;
        float a0 = 0.f, a1 = 0.f, a2 = 0.f, a3 = 0.f;
#pragma unroll 8
        for (int c = 0; c < 32; c++) {
            float v = sX[c * 128 + pix];
            const float4 wv = *(const float4*)&sW0hr[c * 32 + og];
            a0 = fmaf(v, wv.x, a0);
            a1 = fmaf(v, wv.y, a1);
            a2 = fmaf(v, wv.z, a2);
            a3 = fmaf(v, wv.w, a3);
        }
        *(float4*)&sHP[pix * STR + og] = make_float4(a0, a1, a2, a3);
    }
    for (int i = tid; i < 102 * 8; i += 288) {
        int cell = i >> 3;              // 0..101 = 3 rows x 34 cells
        int og   = (i & 7) << 2;
        int lxl  = cell % 34, lyl = cell / 34;
        int glx  = min(max(lx0 - 1 + lxl, 0), LW - 1);
        int gly  = min(max(ly0 - 1 + lyl, 0), LH - 1);
        float4 v = *(const float4*)&g_P[(((size_t)b * LH + gly) * LW + glx) * 32 + og];
        *(float4*)&sP[cell * STR + og] = v;
    }
    __syncthreads();

    // ---- phase 3: warp k = direction k; lane does 4 pixels ----
    {
        const int k    = tid >> 5;          // 0..8
        const int lane = tid & 31;
        const int px   = lane & 3;

        const unsigned NY = (1u<<3)|(1u<<5)|(1u<<6), PY = (1u<<4)|(1u<<7)|(1u<<8);
        const unsigned NX = (1u<<1)|(1u<<5)|(1u<<7), PX = (1u<<2)|(1u<<6)|(1u<<8);
        int dy = (int)((PY >> k) & 1u) - (int)((NY >> k) & 1u);
        int dx = (int)((PX >> k) & 1u) - (int)((NX >> k) & 1u);
        int yn = y + dy * 4;
        bool vy = (yn >= 0) & (yn < H);
        bool valid[4];
#pragma unroll
        for (int p = 0; p < 4; p++) {
            int xn = x0 + lane + p * 32 + dx * 4;
            valid[p] = vy & (xn >= 0) & (xn < W);
        }

        const float* hp0 = &sHP[lane * STR];              // +p*32*STR
        const float* pr0 = &sP[((1 + dy) * 34 + (lane >> 2) + 1 + dx) * STR]; // +p*8*STR
        const float* dtr = &sDT[(k * 4 + px) * STR];

        float h1[4][16];
#pragma unroll
        for (int p = 0; p < 4; p++)
#pragma unroll
            for (int j = 0; j < 16; j++) h1[p][j] = 0.f;

#pragma unroll 1
        for (int c4 = 0; c4 < 32; c4 += 4) {
            const float4 dt4 = *(const float4*)&dtr[c4];
            float a[4][4];
#pragma unroll
            for (int p = 0; p < 4; p++) {
                const float4 h4 = *(const float4*)&hp0[p * 32 * STR + c4];
                const float4 p4 = *(const float4*)&pr0[p * 8 * STR + c4];
                float t;
                t = h4.x + p4.x + dt4.x; a[p][0] = fmaxf(t, 0.01f * t);
                t = h4.y + p4.y + dt4.y; a[p][1] = fmaxf(t, 0.01f * t);
                t = h4.z + p4.z + dt4.z; a[p][2] = fmaxf(t, 0.01f * t);
                t = h4.w + p4.w + dt4.w; a[p][3] = fmaxf(t, 0.01f * t);
            }
#pragma unroll
            for (int cc = 0; cc < 4; cc++) {
                const int c = c4 + cc;
#pragma unroll
                for (int jq = 0; jq < 4; jq++) {
                    const float4 wv = *(const float4*)&sW1[c * 16 + jq * 4];
#pragma unroll
                    for (int p = 0; p < 4; p++) {
                        float v = a[p][cc];
                        h1[p][jq*4+0] = fmaf(v, wv.x, h1[p][jq*4+0]);
                        h1[p][jq*4+1] = fmaf(v, wv.y, h1[p][jq*4+1]);
                        h1[p][jq*4+2] = fmaf(v, wv.z, h1[p][jq*4+2]);
                        h1[p][jq*4+3] = fmaf(v, wv.w, h1[p][jq*4+3]);
                    }
                }
            }
        }

        float h2[4][8];
#pragma unroll
        for (int p = 0; p < 4; p++)
#pragma unroll
            for (int j = 0; j < 8; j++) h2[p][j] = 0.f;
#pragma unroll 2
        for (int c = 0; c < 16; c++) {
            const float4 w2a = *(const float4*)&sW2[c * 8];
            const float4 w2b = *(const float4*)&sW2[c * 8 + 4];
#pragma unroll
            for (int p = 0; p < 4; p++) {
                float v = fmaxf(h1[p][c], 0.01f * h1[p][c]);
                h2[p][0] = fmaf(v, w2a.x, h2[p][0]);
                h2[p][1] = fmaf(v, w2a.y, h2[p][1]);
                h2[p][2] = fmaf(v, w2a.z, h2[p][2]);
                h2[p][3] = fmaf(v, w2a.w, h2[p][3]);
                h2[p][4] = fmaf(v, w2b.x, h2[p][4]);
                h2[p][5] = fmaf(v, w2b.y, h2[p][5]);
                h2[p][6] = fmaf(v, w2b.z, h2[p][6]);
                h2[p][7] = fmaf(v, w2b.w, h2[p][7]);
            }
        }

        float logit[4] = {0.f, 0.f, 0.f, 0.f};
#pragma unroll
        for (int c = 0; c < 8; c++) {
            float wv = sW3[c];
#pragma unroll
            for (int p = 0; p < 4; p++)
                logit[p] = fmaf(fmaxf(h2[p][c], 0.01f * h2[p][c]), wv, logit[p]);
        }

#pragma unroll
        for (int p = 0; p < 4; p++)
            sL[k * 128 + lane + p * 32] = valid[p] ? logit[p] : -100.0f;
    }
    __syncthreads();

    // ---- phase 4: softmax over 9 dirs, write out ----
    if (tid < 128) {
        float v[9], m = -1e30f;
#pragma unroll
        for (int k = 0; k < 9; k++) {
            v[k] = sL[k * 128 + tid];
            m = fmaxf(m, v[k]);
        }
        float s = 0.f;
#pragma unroll
        for (int k = 0; k < 9; k++) {
            v[k] = __expf(v[k] - m);
            s += v[k];
        }
        float inv = 1.f / s;
        float* op = out + (((size_t)b * 9) * H + y) * W + x0 + tid;
#pragma unroll
        for (int k = 0; k < 9; k++)
            op[(size_t)k * H * W] = v[k] * inv;
    }
}

// ---------------------------------------------------------------------------
extern "C" void kernel_launch(void* const* d_in, const int* in_sizes, int n_in,
                              void* d_out, int out_size)
{
    const float* lr = (const float*)d_in[0];
    const float* hr = (const float*)d_in[1];
    // d_in[2], d_in[3] (lr_feature_r / hr_feature_r) unused by the reference
    const float* w0 = (const float*)d_in[4];
    const float* w1 = (const float*)d_in[5];
    const float* w2 = (const float*)d_in[6];
    const float* w3 = (const float*)d_in[7];
    float* out = (float*)d_out;

    cudaFuncSetAttribute(k_main, cudaFuncAttributeMaxDynamicSharedMemorySize,
                         SMEM_FLOATS * (int)sizeof(float));

    k_precompute_P<<<(Bn * LH * LW * 4 + 255) / 256, 256>>>(lr, w0);

    dim3 grid(W / 128, H, Bn);
    k_main<<<grid, 288, SMEM_FLOATS * sizeof(float)>>>(hr, w0, w1, w2, w3, out);
}

// round 9
// speedup vs baseline: 1.2052x; 1.2052x over previous
#include <cuda_runtime.h>
#include <math.h>

#define Bn 2
#define C 32
#define H 256
#define W 512
#define LH 64
#define LW 128

#define STR 36   // activation row stride (floats): 144B, 16B-aligned, bank-rotating

// packed f32x2 helpers (Blackwell sm_103a)
#define FMA2(d, a, b, c) \
    asm("fma.rn.f32x2 %0, %1, %2, %3;" : "=l"(d) : "l"(a), "l"(b), "l"(c))
#define PACK2(d, lo, hi) \
    asm("mov.b64 %0, {%1, %2};" : "=l"(d) : "f"(lo), "f"(hi))
#define UNPACK2(lo, hi, s) \
    asm("mov.b64 {%0, %1}, %2;" : "=f"(lo), "=f"(hi) : "l"(s))

// Precomputed lr projection: P[b][ly][lx][o] = W0_lr @ lr   (2 MB scratch)
__device__ float g_P[Bn * LH * LW * 32];

// ---------------------------------------------------------------------------
// Kernel 1: P[b,ly,lx,o] = sum_c w0[o,c] * lr[b,c,ly,lx]
// ---------------------------------------------------------------------------
__global__ __launch_bounds__(256) void k_precompute_P(
    const float* __restrict__ lr, const float* __restrict__ w0)
{
    __shared__ float sw[32 * 32];  // [c][o]
    int t = threadIdx.x;
    for (int i = t; i < 32 * 32; i += 256) {
        int c = i >> 5, o = i & 31;
        sw[i] = w0[o * 66 + c];
    }
    __syncthreads();

    int gid = blockIdx.x * 256 + t;
    int pix = gid >> 2;
    int og  = (gid & 3) * 8;
    if (pix >= Bn * LH * LW) return;
    int b   = pix / (LH * LW);
    int rem = pix - b * (LH * LW);

    const float* lp = lr + (size_t)b * C * LH * LW + rem;
    float acc[8];
#pragma unroll
    for (int o = 0; o < 8; o++) acc[o] = 0.f;
#pragma unroll
    for (int c = 0; c < 32; c++) {
        float v = lp[c * (LH * LW)];
#pragma unroll
        for (int o = 0; o < 8; o++)
            acc[o] = fmaf(v, sw[c * 32 + og + o], acc[o]);
    }
    float* P = g_P + (size_t)pix * 32 + og;
#pragma unroll
    for (int o = 0; o < 8; o++) P[o] = acc[o];
}

// ---------------------------------------------------------------------------
// Main kernel. Block = 64-pixel strip (one row) x 9 directions.
// 288 threads = 9 warps; warp k owns direction k; lane handles pixels
// lane and lane+32, packed as f32x2 lanes through the MLP (FFMA2).
// Weights stored duplicated (float2) so LDS.128 broadcasts feed FFMA2 directly.
// ---------------------------------------------------------------------------
__global__ __launch_bounds__(288, 3) void k_main(
    const float* __restrict__ hr,
    const float* __restrict__ w0,
    const float* __restrict__ w1,
    const float* __restrict__ w2,
    const float* __restrict__ w3,
    float* __restrict__ out)
{
    __shared__ __align__(16) float sW0hr[32 * 32];   // [c][o]
    __shared__ __align__(16) float sW1d[32 * 32];    // [c][j] duplicated pairs
    __shared__ __align__(16) float sW2d[16 * 16];    // [c][j] duplicated pairs
    __shared__ float sW3[8];
    __shared__ __align__(16) float sX[32 * 64];      // hr tile [c][pix]
    __shared__ __align__(16) float sHP[64 * STR];    // hpart [pix][o]
    __shared__ __align__(16) float sP[54 * STR];     // P halo [3x18 cells][o]
    __shared__ __align__(16) float sDT[36 * STR];    // dt [k*4+px][o]
    __shared__ float sL[9 * 64];                     // logits [k][pix]

    const int tid = threadIdx.x;
    const int x0  = blockIdx.x * 64;
    const int y   = blockIdx.y;
    const int b   = blockIdx.z;
    const int py  = y & 3;
    const int ly0 = y >> 2;
    const int lx0 = x0 >> 2;

    // ---- phase 1: stage weights (dup W1/W2), hr tile, build dt ----
    for (int i = tid; i < 32 * 32; i += 288) {
        int c = i >> 5, o = i & 31;
        sW0hr[i] = w0[o * 66 + 32 + c];
    }
    for (int i = tid; i < 32 * 16; i += 288) {
        int c = i >> 4, j = i & 15;
        float wv = w1[j * 32 + c];
        *(float2*)&sW1d[c * 32 + j * 2] = make_float2(wv, wv);
    }
    for (int i = tid; i < 16 * 8; i += 288) {
        int c = i >> 3, j = i & 7;
        float wv = w2[j * 16 + c];
        *(float2*)&sW2d[c * 16 + j * 2] = make_float2(wv, wv);
    }
    if (tid < 8) sW3[tid] = w3[tid];

    for (int i = tid; i < 32 * 64; i += 288) {
        int c = i >> 6, p = i & 63;
        sX[i] = hr[(((size_t)b * C + c) * H + y) * W + x0 + p];
    }

    {
        float byf = (py < 2) ? (float)(py - 2) : (float)(py - 1);
        for (int i = tid; i < 9 * 4 * 32; i += 288) {
            int o  = i & 31;
            int px = (i >> 5) & 3;
            int k  = i >> 7;
            float bxf = (px < 2) ? (float)(px - 2) : (float)(px - 1);
            float d0, d1;
            if (k == 0)                { d0 = bxf;              d1 = byf;              }
            else if (k == 1 || k == 5) { d0 = 4.f - (float)px;  d1 = byf;              }
            else if (k == 2 || k == 6) { d0 = (float)px + 1.f;  d1 = byf;              }
            else if (k == 3 || k == 7) { d0 = bxf;              d1 = 4.f - (float)py;  }
            else                       { d0 = bxf;              d1 = (float)py + 1.f;  }
            sDT[(k * 4 + px) * STR + o] =
                w0[o * 66 + 64] * d0 + w0[o * 66 + 65] * d1;
        }
    }
    __syncthreads();

    // ---- phase 2: hpart from sX; P halo from g_P (float4 copies) ----
    for (int i = tid; i < 512; i += 288) {
        int pix = i >> 3;
        int og  = (i & 7) << 2;
        float a0 = 0.f, a1 = 0.f, a2 = 0.f, a3 = 0.f;
#pragma unroll 8
        for (int c = 0; c < 32; c++) {
            float v = sX[c * 64 + pix];
            const float4 wv = *(const float4*)&sW0hr[c * 32 + og];
            a0 = fmaf(v, wv.x, a0);
            a1 = fmaf(v, wv.y, a1);
            a2 = fmaf(v, wv.z, a2);
            a3 = fmaf(v, wv.w, a3);
        }
        *(float4*)&sHP[pix * STR + og] = make_float4(a0, a1, a2, a3);
    }
    for (int i = tid; i < 54 * 8; i += 288) {
        int cell = i >> 3;
        int og   = (i & 7) << 2;
        int lxl  = cell % 18, lyl = cell / 18;
        int glx  = min(max(lx0 - 1 + lxl, 0), LW - 1);
        int gly  = min(max(ly0 - 1 + lyl, 0), LH - 1);
        float4 v = *(const float4*)&g_P[(((size_t)b * LH + gly) * LW + glx) * 32 + og];
        *(float4*)&sP[cell * STR + og] = v;
    }
    __syncthreads();

    // ---- phase 3: warp k = direction k; lane does pixels lane, lane+32 ----
    {
        const int k    = tid >> 5;          // 0..8
        const int lane = tid & 31;
        const int pA   = lane;
        const int pB   = lane + 32;
        const int px   = pA & 3;

        // dir offsets: dy=-1 k in {3,5,6}, dy=+1 {4,7,8}; dx=-1 {1,5,7}, dx=+1 {2,6,8}
        const unsigned NY = (1u<<3)|(1u<<5)|(1u<<6), PY = (1u<<4)|(1u<<7)|(1u<<8);
        const unsigned NX = (1u<<1)|(1u<<5)|(1u<<7), PX = (1u<<2)|(1u<<6)|(1u<<8);
        int dy = (int)((PY >> k) & 1u) - (int)((NY >> k) & 1u);
        int dx = (int)((PX >> k) & 1u) - (int)((NX >> k) & 1u);
        int yn = y + dy * 4;
        bool vy = (yn >= 0) & (yn < H);
        int xnA = x0 + pA + dx * 4;
        int xnB = x0 + pB + dx * 4;
        bool validA = vy & (xnA >= 0) & (xnA < W);
        bool validB = vy & (xnB >= 0) & (xnB < W);

        const float* hpA = &sHP[pA * STR];
        const float* hpB = &sHP[pB * STR];
        const float* prA = &sP[((1 + dy) * 18 + (pA >> 2) + 1 + dx) * STR];
        const float* prB = prA + 8 * STR;
        const float* dtr = &sDT[(k * 4 + px) * STR];

        unsigned long long h1p[16];
#pragma unroll
        for (int j = 0; j < 16; j++) h1p[j] = 0ULL;

#pragma unroll 2
        for (int c4 = 0; c4 < 32; c4 += 4) {
            const float4 hA4 = *(const float4*)&hpA[c4];
            const float4 hB4 = *(const float4*)&hpB[c4];
            const float4 pA4 = *(const float4*)&prA[c4];
            const float4 pB4 = *(const float4*)&prB[c4];
            const float4 dt4 = *(const float4*)&dtr[c4];

            unsigned long long ap[4];
            {
                float tA, tB, aA, aB;
                tA = hA4.x + pA4.x + dt4.x; aA = fmaxf(tA, 0.01f * tA);
                tB = hB4.x + pB4.x + dt4.x; aB = fmaxf(tB, 0.01f * tB);
                PACK2(ap[0], aA, aB);
                tA = hA4.y + pA4.y + dt4.y; aA = fmaxf(tA, 0.01f * tA);
                tB = hB4.y + pB4.y + dt4.y; aB = fmaxf(tB, 0.01f * tB);
                PACK2(ap[1], aA, aB);
                tA = hA4.z + pA4.z + dt4.z; aA = fmaxf(tA, 0.01f * tA);
                tB = hB4.z + pB4.z + dt4.z; aB = fmaxf(tB, 0.01f * tB);
                PACK2(ap[2], aA, aB);
                tA = hA4.w + pA4.w + dt4.w; aA = fmaxf(tA, 0.01f * tA);
                tB = hB4.w + pB4.w + dt4.w; aB = fmaxf(tB, 0.01f * tB);
                PACK2(ap[3], aA, aB);
            }
#pragma unroll
            for (int cc = 0; cc < 4; cc++) {
                const int c = c4 + cc;
                const ulonglong2* wp = (const ulonglong2*)&sW1d[c * 32];
                unsigned long long av = ap[cc];
#pragma unroll
                for (int jq = 0; jq < 8; jq++) {
                    ulonglong2 wv = wp[jq];      // LDS.128 broadcast: 2 dup weights
                    FMA2(h1p[jq * 2 + 0], av, wv.x, h1p[jq * 2 + 0]);
                    FMA2(h1p[jq * 2 + 1], av, wv.y, h1p[jq * 2 + 1]);
                }
            }
        }

        unsigned long long h2p[8];
#pragma unroll
        for (int j = 0; j < 8; j++) h2p[j] = 0ULL;
#pragma unroll 4
        for (int c = 0; c < 16; c++) {
            float vA, vB;
            UNPACK2(vA, vB, h1p[c]);
            vA = fmaxf(vA, 0.01f * vA);
            vB = fmaxf(vB, 0.01f * vB);
            unsigned long long av;
            PACK2(av, vA, vB);
            const ulonglong2* wp = (const ulonglong2*)&sW2d[c * 16];
#pragma unroll
            for (int jq = 0; jq < 4; jq++) {
                ulonglong2 wv = wp[jq];
                FMA2(h2p[jq * 2 + 0], av, wv.x, h2p[jq * 2 + 0]);
                FMA2(h2p[jq * 2 + 1], av, wv.y, h2p[jq * 2 + 1]);
            }
        }

        float logitA = 0.f, logitB = 0.f;
#pragma unroll
        for (int c = 0; c < 8; c++) {
            float vA, vB;
            UNPACK2(vA, vB, h2p[c]);
            float wv = sW3[c];
            logitA = fmaf(fmaxf(vA, 0.01f * vA), wv, logitA);
            logitB = fmaf(fmaxf(vB, 0.01f * vB), wv, logitB);
        }

        sL[k * 64 + pA] = validA ? logitA : -100.0f;
        sL[k * 64 + pB] = validB ? logitB : -100.0f;
    }
    __syncthreads();

    // ---- phase 4: softmax over 9 dirs, write out ----
    if (tid < 64) {
        float v[9], m = -1e30f;
#pragma unroll
        for (int k = 0; k < 9; k++) {
            v[k] = sL[k * 64 + tid];
            m = fmaxf(m, v[k]);
        }
        float s = 0.f;
#pragma unroll
        for (int k = 0; k < 9; k++) {
            v[k] = __expf(v[k] - m);
            s += v[k];
        }
        float inv = 1.f / s;
        float* op = out + (((size_t)b * 9) * H + y) * W + x0 + tid;
#pragma unroll
        for (int k = 0; k < 9; k++)
            op[(size_t)k * H * W] = v[k] * inv;
    }
}

// ---------------------------------------------------------------------------
extern "C" void kernel_launch(void* const* d_in, const int* in_sizes, int n_in,
                              void* d_out, int out_size)
{
    const float* lr = (const float*)d_in[0];
    const float* hr = (const float*)d_in[1];
    // d_in[2], d_in[3] (lr_feature_r / hr_feature_r) unused by the reference
    const float* w0 = (const float*)d_in[4];
    const float* w1 = (const float*)d_in[5];
    const float* w2 = (const float*)d_in[6];
    const float* w3 = (const float*)d_in[7];
    float* out = (float*)d_out;

    k_precompute_P<<<(Bn * LH * LW * 4 + 255) / 256, 256>>>(lr, w0);

    dim3 grid(W / 64, H, Bn);
    k_main<<<grid, 288>>>(hr, w0, w1, w2, w3, out);
}

// round 10
// speedup vs baseline: 1.5218x; 1.2627x over previous
#include <cuda_runtime.h>
#include <math.h>

#define Bn 2
#define C 32
#define H 256
#define W 512
#define LH 64
#define LW 128

#define STR 36   // activation row stride (floats): 144B, 16B-aligned, bank-rotating

// packed f32x2 helpers (Blackwell sm_103a)
#define FMA2(d, a, b, c) \
    asm("fma.rn.f32x2 %0, %1, %2, %3;" : "=l"(d) : "l"(a), "l"(b), "l"(c))
#define PACK2(d, lo, hi) \
    asm("mov.b64 %0, {%1, %2};" : "=l"(d) : "f"(lo), "f"(hi))
#define UNPACK2(lo, hi, s) \
    asm("mov.b64 {%0, %1}, %2;" : "=f"(lo), "=f"(hi) : "l"(s))

// Precomputed lr projection: P[b][ly][lx][o] = W0_lr @ lr   (2 MB scratch)
__device__ float g_P[Bn * LH * LW * 32];

// ---------------------------------------------------------------------------
// Kernel 1: P[b,ly,lx,o] = sum_c w0[o,c] * lr[b,c,ly,lx]
// ---------------------------------------------------------------------------
__global__ __launch_bounds__(256) void k_precompute_P(
    const float* __restrict__ lr, const float* __restrict__ w0)
{
    __shared__ float sw[32 * 32];  // [c][o]
    int t = threadIdx.x;
    for (int i = t; i < 32 * 32; i += 256) {
        int c = i >> 5, o = i & 31;
        sw[i] = w0[o * 66 + c];
    }
    __syncthreads();

    int gid = blockIdx.x * 256 + t;
    int pix = gid >> 2;
    int og  = (gid & 3) * 8;
    if (pix >= Bn * LH * LW) return;
    int b   = pix / (LH * LW);
    int rem = pix - b * (LH * LW);

    const float* lp = lr + (size_t)b * C * LH * LW + rem;
    float acc[8];
#pragma unroll
    for (int o = 0; o < 8; o++) acc[o] = 0.f;
#pragma unroll
    for (int c = 0; c < 32; c++) {
        float v = lp[c * (LH * LW)];
#pragma unroll
        for (int o = 0; o < 8; o++)
            acc[o] = fmaf(v, sw[c * 32 + og + o], acc[o]);
    }
    float* P = g_P + (size_t)pix * 32 + og;
#pragma unroll
    for (int o = 0; o < 8; o++) P[o] = acc[o];
}

// ---------------------------------------------------------------------------
// Main kernel. Block = 64-pixel strip (one row) x 9 directions.
// 288 threads = 9 warps; warp k owns direction k; lane handles pixels
// lane and lane+32. FFMA2 pairs the two OUTPUT channels (j, j+1), so plain
// weight rows feed f32x2 directly (no duplication, weight LDS unchanged).
// ---------------------------------------------------------------------------
__global__ __launch_bounds__(288, 3) void k_main(
    const float* __restrict__ hr,
    const float* __restrict__ w0,
    const float* __restrict__ w1,
    const float* __restrict__ w2,
    const float* __restrict__ w3,
    float* __restrict__ out)
{
    __shared__ __align__(16) float sW0hr[32 * 32];   // [c][o]
    __shared__ __align__(16) float sW1[32 * 16];     // [c][j]
    __shared__ __align__(16) float sW2[16 * 8];      // [c][j]
    __shared__ float sW3[8];
    __shared__ __align__(16) float sX[32 * 64];      // hr tile [c][pix]
    __shared__ __align__(16) float sHP[64 * STR];    // hpart [pix][o]
    __shared__ __align__(16) float sP[54 * STR];     // P halo [3x18 cells][o]
    __shared__ __align__(16) float sDT[36 * STR];    // dt [k*4+px][o]
    __shared__ float sL[9 * 64];                     // logits [k][pix]

    const int tid = threadIdx.x;
    const int x0  = blockIdx.x * 64;
    const int y   = blockIdx.y;
    const int b   = blockIdx.z;
    const int py  = y & 3;
    const int ly0 = y >> 2;
    const int lx0 = x0 >> 2;

    // ---- phase 1: stage weights, hr tile, build dt ----
    for (int i = tid; i < 32 * 32; i += 288) {
        int c = i >> 5, o = i & 31;
        sW0hr[i] = w0[o * 66 + 32 + c];
    }
    for (int i = tid; i < 32 * 16; i += 288) {
        int c = i >> 4, j = i & 15;
        sW1[i] = w1[j * 32 + c];
    }
    for (int i = tid; i < 16 * 8; i += 288) {
        int c = i >> 3, j = i & 7;
        sW2[i] = w2[j * 16 + c];
    }
    if (tid < 8) sW3[tid] = w3[tid];

    for (int i = tid; i < 32 * 64; i += 288) {
        int c = i >> 6, p = i & 63;
        sX[i] = hr[(((size_t)b * C + c) * H + y) * W + x0 + p];
    }

    {
        float byf = (py < 2) ? (float)(py - 2) : (float)(py - 1);
        for (int i = tid; i < 9 * 4 * 32; i += 288) {
            int o  = i & 31;
            int px = (i >> 5) & 3;
            int k  = i >> 7;
            float bxf = (px < 2) ? (float)(px - 2) : (float)(px - 1);
            float d0, d1;
            if (k == 0)                { d0 = bxf;              d1 = byf;              }
            else if (k == 1 || k == 5) { d0 = 4.f - (float)px;  d1 = byf;              }
            else if (k == 2 || k == 6) { d0 = (float)px + 1.f;  d1 = byf;              }
            else if (k == 3 || k == 7) { d0 = bxf;              d1 = 4.f - (float)py;  }
            else                       { d0 = bxf;              d1 = (float)py + 1.f;  }
            sDT[(k * 4 + px) * STR + o] =
                w0[o * 66 + 64] * d0 + w0[o * 66 + 65] * d1;
        }
    }
    __syncthreads();

    // ---- phase 2: hpart from sX; P halo from g_P (float4 copies) ----
    for (int i = tid; i < 512; i += 288) {
        int pix = i >> 3;
        int og  = (i & 7) << 2;
        float a0 = 0.f, a1 = 0.f, a2 = 0.f, a3 = 0.f;
#pragma unroll 8
        for (int c = 0; c < 32; c++) {
            float v = sX[c * 64 + pix];
            const float4 wv = *(const float4*)&sW0hr[c * 32 + og];
            a0 = fmaf(v, wv.x, a0);
            a1 = fmaf(v, wv.y, a1);
            a2 = fmaf(v, wv.z, a2);
            a3 = fmaf(v, wv.w, a3);
        }
        *(float4*)&sHP[pix * STR + og] = make_float4(a0, a1, a2, a3);
    }
    for (int i = tid; i < 54 * 8; i += 288) {
        int cell = i >> 3;
        int og   = (i & 7) << 2;
        int lxl  = cell % 18, lyl = cell / 18;
        int glx  = min(max(lx0 - 1 + lxl, 0), LW - 1);
        int gly  = min(max(ly0 - 1 + lyl, 0), LH - 1);
        float4 v = *(const float4*)&g_P[(((size_t)b * LH + gly) * LW + glx) * 32 + og];
        *(float4*)&sP[cell * STR + og] = v;
    }
    __syncthreads();

    // ---- phase 3: warp k = direction k; lane does pixels lane, lane+32 ----
    {
        const int k    = tid >> 5;          // 0..8
        const int lane = tid & 31;
        const int pA   = lane;
        const int pB   = lane + 32;
        const int px   = pA & 3;

        // dir offsets: dy=-1 k in {3,5,6}, dy=+1 {4,7,8}; dx=-1 {1,5,7}, dx=+1 {2,6,8}
        const unsigned NY = (1u<<3)|(1u<<5)|(1u<<6), PY = (1u<<4)|(1u<<7)|(1u<<8);
        const unsigned NX = (1u<<1)|(1u<<5)|(1u<<7), PX = (1u<<2)|(1u<<6)|(1u<<8);
        int dy = (int)((PY >> k) & 1u) - (int)((NY >> k) & 1u);
        int dx = (int)((PX >> k) & 1u) - (int)((NX >> k) & 1u);
        int yn = y + dy * 4;
        bool vy = (yn >= 0) & (yn < H);
        int xnA = x0 + pA + dx * 4;
        int xnB = x0 + pB + dx * 4;
        bool validA = vy & (xnA >= 0) & (xnA < W);
        bool validB = vy & (xnB >= 0) & (xnB < W);

        const float* hpA = &sHP[pA * STR];
        const float* hpB = &sHP[pB * STR];
        const float* prA = &sP[((1 + dy) * 18 + (pA >> 2) + 1 + dx) * STR];
        const float* prB = prA + 8 * STR;
        const float* dtr = &sDT[(k * 4 + px) * STR];

        // h1 accumulators: 8 channel-pairs per pixel (j,j+1) packed f32x2
        unsigned long long h1A[8], h1B[8];
#pragma unroll
        for (int j = 0; j < 8; j++) { h1A[j] = 0ULL; h1B[j] = 0ULL; }

#pragma unroll 2
        for (int c4 = 0; c4 < 32; c4 += 4) {
            const float4 hA4 = *(const float4*)&hpA[c4];
            const float4 hB4 = *(const float4*)&hpB[c4];
            const float4 pA4 = *(const float4*)&prA[c4];
            const float4 pB4 = *(const float4*)&prB[c4];
            const float4 dt4 = *(const float4*)&dtr[c4];

            float aA[4], aB[4];
            {
                float t;
                t = hA4.x + pA4.x + dt4.x; aA[0] = fmaxf(t, 0.01f * t);
                t = hA4.y + pA4.y + dt4.y; aA[1] = fmaxf(t, 0.01f * t);
                t = hA4.z + pA4.z + dt4.z; aA[2] = fmaxf(t, 0.01f * t);
                t = hA4.w + pA4.w + dt4.w; aA[3] = fmaxf(t, 0.01f * t);
                t = hB4.x + pB4.x + dt4.x; aB[0] = fmaxf(t, 0.01f * t);
                t = hB4.y + pB4.y + dt4.y; aB[1] = fmaxf(t, 0.01f * t);
                t = hB4.z + pB4.z + dt4.z; aB[2] = fmaxf(t, 0.01f * t);
                t = hB4.w + pB4.w + dt4.w; aB[3] = fmaxf(t, 0.01f * t);
            }
#pragma unroll
            for (int cc = 0; cc < 4; cc++) {
                const int c = c4 + cc;
                const ulonglong2* wp = (const ulonglong2*)&sW1[c * 16];
                unsigned long long apA, apB;
                PACK2(apA, aA[cc], aA[cc]);
                PACK2(apB, aB[cc], aB[cc]);
#pragma unroll
                for (int q = 0; q < 4; q++) {
                    ulonglong2 wv = wp[q];     // pairs (w[4q],w[4q+1]),(w[4q+2],w[4q+3])
                    FMA2(h1A[q * 2 + 0], apA, wv.x, h1A[q * 2 + 0]);
                    FMA2(h1A[q * 2 + 1], apA, wv.y, h1A[q * 2 + 1]);
                    FMA2(h1B[q * 2 + 0], apB, wv.x, h1B[q * 2 + 0]);
                    FMA2(h1B[q * 2 + 1], apB, wv.y, h1B[q * 2 + 1]);
                }
            }
        }

        // layer 2: h2 accumulators = 4 channel-pairs per pixel
        unsigned long long h2A[4], h2B[4];
#pragma unroll
        for (int j = 0; j < 4; j++) { h2A[j] = 0ULL; h2B[j] = 0ULL; }
#pragma unroll 2
        for (int c2 = 0; c2 < 8; c2++) {       // h1 pair index: channels 2c2, 2c2+1
            float uA0, uA1, uB0, uB1;
            UNPACK2(uA0, uA1, h1A[c2]);
            UNPACK2(uB0, uB1, h1B[c2]);
            uA0 = fmaxf(uA0, 0.01f * uA0);  uA1 = fmaxf(uA1, 0.01f * uA1);
            uB0 = fmaxf(uB0, 0.01f * uB0);  uB1 = fmaxf(uB1, 0.01f * uB1);
            unsigned long long aA0, aA1, aB0, aB1;
            PACK2(aA0, uA0, uA0); PACK2(aA1, uA1, uA1);
            PACK2(aB0, uB0, uB0); PACK2(aB1, uB1, uB1);

            const ulonglong2* wp0 = (const ulonglong2*)&sW2[(2 * c2) * 8];
            const ulonglong2* wp1 = (const ulonglong2*)&sW2[(2 * c2 + 1) * 8];
            ulonglong2 w0v = wp0[0], w0w = wp0[1];
            ulonglong2 w1v = wp1[0], w1w = wp1[1];
            FMA2(h2A[0], aA0, w0v.x, h2A[0]); FMA2(h2A[1], aA0, w0v.y, h2A[1]);
            FMA2(h2A[2], aA0, w0w.x, h2A[2]); FMA2(h2A[3], aA0, w0w.y, h2A[3]);
            FMA2(h2A[0], aA1, w1v.x, h2A[0]); FMA2(h2A[1], aA1, w1v.y, h2A[1]);
            FMA2(h2A[2], aA1, w1w.x, h2A[2]); FMA2(h2A[3], aA1, w1w.y, h2A[3]);
            FMA2(h2B[0], aB0, w0v.x, h2B[0]); FMA2(h2B[1], aB0, w0v.y, h2B[1]);
            FMA2(h2B[2], aB0, w0w.x, h2B[2]); FMA2(h2B[3], aB0, w0w.y, h2B[3]);
            FMA2(h2B[0], aB1, w1v.x, h2B[0]); FMA2(h2B[1], aB1, w1v.y, h2B[1]);
            FMA2(h2B[2], aB1, w1w.x, h2B[2]); FMA2(h2B[3], aB1, w1w.y, h2B[3]);
        }

        // layer 3
        float logitA = 0.f, logitB = 0.f;
#pragma unroll
        for (int j = 0; j < 4; j++) {
            float vA0, vA1, vB0, vB1;
            UNPACK2(vA0, vA1, h2A[j]);
            UNPACK2(vB0, vB1, h2B[j]);
            float w30 = sW3[2 * j], w31 = sW3[2 * j + 1];
            logitA = fmaf(fmaxf(vA0, 0.01f * vA0), w30, logitA);
            logitA = fmaf(fmaxf(vA1, 0.01f * vA1), w31, logitA);
            logitB = fmaf(fmaxf(vB0, 0.01f * vB0), w30, logitB);
            logitB = fmaf(fmaxf(vB1, 0.01f * vB1), w31, logitB);
        }

        sL[k * 64 + pA] = validA ? logitA : -100.0f;
        sL[k * 64 + pB] = validB ? logitB : -100.0f;
    }
    __syncthreads();

    // ---- phase 4: softmax over 9 dirs, write out ----
    if (tid < 64) {
        float v[9], m = -1e30f;
#pragma unroll
        for (int k = 0; k < 9; k++) {
            v[k] = sL[k * 64 + tid];
            m = fmaxf(m, v[k]);
        }
        float s = 0.f;
#pragma unroll
        for (int k = 0; k < 9; k++) {
            v[k] = __expf(v[k] - m);
            s += v[k];
        }
        float inv = 1.f / s;
        float* op = out + (((size_t)b * 9) * H + y) * W + x0 + tid;
#pragma unroll
        for (int k = 0; k < 9; k++)
            op[(size_t)k * H * W] = v[k] * inv;
    }
}

// ---------------------------------------------------------------------------
extern "C" void kernel_launch(void* const* d_in, const int* in_sizes, int n_in,
                              void* d_out, int out_size)
{
    const float* lr = (const float*)d_in[0];
    const float* hr = (const float*)d_in[1];
    // d_in[2], d_in[3] (lr_feature_r / hr_feature_r) unused by the reference
    const float* w0 = (const float*)d_in[4];
    const float* w1 = (const float*)d_in[5];
    const float* w2 = (const float*)d_in[6];
    const float* w3 = (const float*)d_in[7];
    float* out = (float*)d_out;

    k_precompute_P<<<(Bn * LH * LW * 4 + 255) / 256, 256>>>(lr, w0);

    dim3 grid(W / 64, H, Bn);
    k_main<<<grid, 288>>>(hr, w0, w1, w2, w3, out);
}

// round 11
// speedup vs baseline: 1.8887x; 1.2411x over previous
#include <cuda_runtime.h>
#include <math.h>

#define Bn 2
#define C 32
#define H 256
#define W 512
#define LH 64
#define LW 128

#define STR 36   // activation row stride (floats): 144B, 16B-aligned, bank-rotating

// packed f32x2 helpers (Blackwell sm_103a)
#define FMA2(d, a, b, c) \
    asm("fma.rn.f32x2 %0, %1, %2, %3;" : "=l"(d) : "l"(a), "l"(b), "l"(c))
#define PACK2(d, lo, hi) \
    asm("mov.b64 %0, {%1, %2};" : "=l"(d) : "f"(lo), "f"(hi))
#define UNPACK2(lo, hi, s) \
    asm("mov.b64 {%0, %1}, %2;" : "=f"(lo), "=f"(hi) : "l"(s))

// Weights in constant memory ([c][j] layouts), fed via staging + memcpyToSymbol
__constant__ float cW1[32 * 16];
__constant__ float cW2[16 * 8];
__constant__ float cW3[8];

__device__ float g_W1t[32 * 16];
__device__ float g_W2t[16 * 8];

// Precomputed lr projection: P[b][ly][lx][o] = W0_lr @ lr   (2 MB scratch)
__device__ float g_P[Bn * LH * LW * 32];

// ---------------------------------------------------------------------------
// Prep: transpose w1/w2 into [c][j] staging buffers.
// ---------------------------------------------------------------------------
__global__ void k_prep_w(const float* __restrict__ w1, const float* __restrict__ w2)
{
    int t = threadIdx.x;
    if (t < 512) { int c = t >> 4, j = t & 15; g_W1t[c * 16 + j] = w1[j * 32 + c]; }
    if (t < 128) { int c = t >> 3, j = t & 7;  g_W2t[c * 8 + j]  = w2[j * 16 + c]; }
}

// ---------------------------------------------------------------------------
// Kernel 1: P[b,ly,lx,o] = sum_c w0[o,c] * lr[b,c,ly,lx]
// ---------------------------------------------------------------------------
__global__ __launch_bounds__(256) void k_precompute_P(
    const float* __restrict__ lr, const float* __restrict__ w0)
{
    __shared__ float sw[32 * 32];  // [c][o]
    int t = threadIdx.x;
    for (int i = t; i < 32 * 32; i += 256) {
        int c = i >> 5, o = i & 31;
        sw[i] = w0[o * 66 + c];
    }
    __syncthreads();

    int gid = blockIdx.x * 256 + t;
    int pix = gid >> 2;
    int og  = (gid & 3) * 8;
    if (pix >= Bn * LH * LW) return;
    int b   = pix / (LH * LW);
    int rem = pix - b * (LH * LW);

    const float* lp = lr + (size_t)b * C * LH * LW + rem;
    float acc[8];
#pragma unroll
    for (int o = 0; o < 8; o++) acc[o] = 0.f;
#pragma unroll
    for (int c = 0; c < 32; c++) {
        float v = lp[c * (LH * LW)];
#pragma unroll
        for (int o = 0; o < 8; o++)
            acc[o] = fmaf(v, sw[c * 32 + og + o], acc[o]);
    }
    float* P = g_P + (size_t)pix * 32 + og;
#pragma unroll
    for (int o = 0; o < 8; o++) P[o] = acc[o];
}

// ---------------------------------------------------------------------------
// Main kernel. Block = 64-pixel strip (one row) x 9 directions.
// 288 threads = 9 warps; warp k owns direction k; lane handles pixels
// lane and lane+32. FFMA2 pairs output channels (j, j+1); weight pairs come
// from CONSTANT memory (warp-uniform -> LDCU uniform port, off the crossbar).
// ---------------------------------------------------------------------------
__global__ __launch_bounds__(288, 3) void k_main(
    const float* __restrict__ hr,
    const float* __restrict__ w0,
    float* __restrict__ out)
{
    __shared__ __align__(16) float sW0hr[32 * 32];   // [c][o]
    __shared__ __align__(16) float sX[32 * 64];      // hr tile [c][pix]
    __shared__ __align__(16) float sHP[64 * STR];    // hpart [pix][o]
    __shared__ __align__(16) float sP[54 * STR];     // P halo [3x18 cells][o]
    __shared__ __align__(16) float sDT[36 * STR];    // dt [k*4+px][o]
    __shared__ float sL[9 * 64];                     // logits [k][pix]

    const int tid = threadIdx.x;
    const int x0  = blockIdx.x * 64;
    const int y   = blockIdx.y;
    const int b   = blockIdx.z;
    const int py  = y & 3;
    const int ly0 = y >> 2;
    const int lx0 = x0 >> 2;

    // ---- phase 1: stage W0hr, hr tile, build dt ----
    for (int i = tid; i < 32 * 32; i += 288) {
        int c = i >> 5, o = i & 31;
        sW0hr[i] = w0[o * 66 + 32 + c];
    }

    for (int i = tid; i < 32 * 64; i += 288) {
        int c = i >> 6, p = i & 63;
        sX[i] = hr[(((size_t)b * C + c) * H + y) * W + x0 + p];
    }

    {
        float byf = (py < 2) ? (float)(py - 2) : (float)(py - 1);
        for (int i = tid; i < 9 * 4 * 32; i += 288) {
            int o  = i & 31;
            int px = (i >> 5) & 3;
            int k  = i >> 7;
            float bxf = (px < 2) ? (float)(px - 2) : (float)(px - 1);
            float d0, d1;
            if (k == 0)                { d0 = bxf;              d1 = byf;              }
            else if (k == 1 || k == 5) { d0 = 4.f - (float)px;  d1 = byf;              }
            else if (k == 2 || k == 6) { d0 = (float)px + 1.f;  d1 = byf;              }
            else if (k == 3 || k == 7) { d0 = bxf;              d1 = 4.f - (float)py;  }
            else                       { d0 = bxf;              d1 = (float)py + 1.f;  }
            sDT[(k * 4 + px) * STR + o] =
                w0[o * 66 + 64] * d0 + w0[o * 66 + 65] * d1;
        }
    }
    __syncthreads();

    // ---- phase 2: hpart from sX; P halo from g_P (float4 copies) ----
    for (int i = tid; i < 512; i += 288) {
        int pix = i >> 3;
        int og  = (i & 7) << 2;
        float a0 = 0.f, a1 = 0.f, a2 = 0.f, a3 = 0.f;
#pragma unroll 8
        for (int c = 0; c < 32; c++) {
            float v = sX[c * 64 + pix];
            const float4 wv = *(const float4*)&sW0hr[c * 32 + og];
            a0 = fmaf(v, wv.x, a0);
            a1 = fmaf(v, wv.y, a1);
            a2 = fmaf(v, wv.z, a2);
            a3 = fmaf(v, wv.w, a3);
        }
        *(float4*)&sHP[pix * STR + og] = make_float4(a0, a1, a2, a3);
    }
    for (int i = tid; i < 54 * 8; i += 288) {
        int cell = i >> 3;
        int og   = (i & 7) << 2;
        int lxl  = cell % 18, lyl = cell / 18;
        int glx  = min(max(lx0 - 1 + lxl, 0), LW - 1);
        int gly  = min(max(ly0 - 1 + lyl, 0), LH - 1);
        float4 v = *(const float4*)&g_P[(((size_t)b * LH + gly) * LW + glx) * 32 + og];
        *(float4*)&sP[cell * STR + og] = v;
    }
    __syncthreads();

    // ---- phase 3: warp k = direction k; lane does pixels lane, lane+32 ----
    {
        const int k    = tid >> 5;          // 0..8
        const int lane = tid & 31;
        const int pA   = lane;
        const int pB   = lane + 32;
        const int px   = pA & 3;

        // dir offsets: dy=-1 k in {3,5,6}, dy=+1 {4,7,8}; dx=-1 {1,5,7}, dx=+1 {2,6,8}
        const unsigned NY = (1u<<3)|(1u<<5)|(1u<<6), PY = (1u<<4)|(1u<<7)|(1u<<8);
        const unsigned NX = (1u<<1)|(1u<<5)|(1u<<7), PX = (1u<<2)|(1u<<6)|(1u<<8);
        int dy = (int)((PY >> k) & 1u) - (int)((NY >> k) & 1u);
        int dx = (int)((PX >> k) & 1u) - (int)((NX >> k) & 1u);
        int yn = y + dy * 4;
        bool vy = (yn >= 0) & (yn < H);
        int xnA = x0 + pA + dx * 4;
        int xnB = x0 + pB + dx * 4;
        bool validA = vy & (xnA >= 0) & (xnA < W);
        bool validB = vy & (xnB >= 0) & (xnB < W);

        const float* hpA = &sHP[pA * STR];
        const float* hpB = &sHP[pB * STR];
        const float* prA = &sP[((1 + dy) * 18 + (pA >> 2) + 1 + dx) * STR];
        const float* prB = prA + 8 * STR;
        const float* dtr = &sDT[(k * 4 + px) * STR];

        // h1 accumulators: 8 channel-pairs per pixel (j,j+1) packed f32x2
        unsigned long long h1A[8], h1B[8];
#pragma unroll
        for (int j = 0; j < 8; j++) { h1A[j] = 0ULL; h1B[j] = 0ULL; }

#pragma unroll 2
        for (int c4 = 0; c4 < 32; c4 += 4) {
            const float4 hA4 = *(const float4*)&hpA[c4];
            const float4 hB4 = *(const float4*)&hpB[c4];
            const float4 pA4 = *(const float4*)&prA[c4];
            const float4 pB4 = *(const float4*)&prB[c4];
            const float4 dt4 = *(const float4*)&dtr[c4];

            float aA[4], aB[4];
            {
                float t;
                t = hA4.x + pA4.x + dt4.x; aA[0] = fmaxf(t, 0.01f * t);
                t = hA4.y + pA4.y + dt4.y; aA[1] = fmaxf(t, 0.01f * t);
                t = hA4.z + pA4.z + dt4.z; aA[2] = fmaxf(t, 0.01f * t);
                t = hA4.w + pA4.w + dt4.w; aA[3] = fmaxf(t, 0.01f * t);
                t = hB4.x + pB4.x + dt4.x; aB[0] = fmaxf(t, 0.01f * t);
                t = hB4.y + pB4.y + dt4.y; aB[1] = fmaxf(t, 0.01f * t);
                t = hB4.z + pB4.z + dt4.z; aB[2] = fmaxf(t, 0.01f * t);
                t = hB4.w + pB4.w + dt4.w; aB[3] = fmaxf(t, 0.01f * t);
            }
#pragma unroll
            for (int cc = 0; cc < 4; cc++) {
                const int c = c4 + cc;
                const ulonglong2* wp = (const ulonglong2*)&cW1[c * 16];
                unsigned long long apA, apB;
                PACK2(apA, aA[cc], aA[cc]);
                PACK2(apB, aB[cc], aB[cc]);
#pragma unroll
                for (int q = 0; q < 4; q++) {
                    ulonglong2 wv = wp[q];     // const-port load, warp-uniform
                    FMA2(h1A[q * 2 + 0], apA, wv.x, h1A[q * 2 + 0]);
                    FMA2(h1A[q * 2 + 1], apA, wv.y, h1A[q * 2 + 1]);
                    FMA2(h1B[q * 2 + 0], apB, wv.x, h1B[q * 2 + 0]);
                    FMA2(h1B[q * 2 + 1], apB, wv.y, h1B[q * 2 + 1]);
                }
            }
        }

        // layer 2: h2 accumulators = 4 channel-pairs per pixel
        unsigned long long h2A[4], h2B[4];
#pragma unroll
        for (int j = 0; j < 4; j++) { h2A[j] = 0ULL; h2B[j] = 0ULL; }
#pragma unroll 2
        for (int c2 = 0; c2 < 8; c2++) {       // h1 pair index: channels 2c2, 2c2+1
            float uA0, uA1, uB0, uB1;
            UNPACK2(uA0, uA1, h1A[c2]);
            UNPACK2(uB0, uB1, h1B[c2]);
            uA0 = fmaxf(uA0, 0.01f * uA0);  uA1 = fmaxf(uA1, 0.01f * uA1);
            uB0 = fmaxf(uB0, 0.01f * uB0);  uB1 = fmaxf(uB1, 0.01f * uB1);
            unsigned long long aA0, aA1, aB0, aB1;
            PACK2(aA0, uA0, uA0); PACK2(aA1, uA1, uA1);
            PACK2(aB0, uB0, uB0); PACK2(aB1, uB1, uB1);

            const ulonglong2* wp0 = (const ulonglong2*)&cW2[(2 * c2) * 8];
            const ulonglong2* wp1 = (const ulonglong2*)&cW2[(2 * c2 + 1) * 8];
            ulonglong2 w0v = wp0[0], w0w = wp0[1];
            ulonglong2 w1v = wp1[0], w1w = wp1[1];
            FMA2(h2A[0], aA0, w0v.x, h2A[0]); FMA2(h2A[1], aA0, w0v.y, h2A[1]);
            FMA2(h2A[2], aA0, w0w.x, h2A[2]); FMA2(h2A[3], aA0, w0w.y, h2A[3]);
            FMA2(h2A[0], aA1, w1v.x, h2A[0]); FMA2(h2A[1], aA1, w1v.y, h2A[1]);
            FMA2(h2A[2], aA1, w1w.x, h2A[2]); FMA2(h2A[3], aA1, w1w.y, h2A[3]);
            FMA2(h2B[0], aB0, w0v.x, h2B[0]); FMA2(h2B[1], aB0, w0v.y, h2B[1]);
            FMA2(h2B[2], aB0, w0w.x, h2B[2]); FMA2(h2B[3], aB0, w0w.y, h2B[3]);
            FMA2(h2B[0], aB1, w1v.x, h2B[0]); FMA2(h2B[1], aB1, w1v.y, h2B[1]);
            FMA2(h2B[2], aB1, w1w.x, h2B[2]); FMA2(h2B[3], aB1, w1w.y, h2B[3]);
        }

        // layer 3
        float logitA = 0.f, logitB = 0.f;
#pragma unroll
        for (int j = 0; j < 4; j++) {
            float vA0, vA1, vB0, vB1;
            UNPACK2(vA0, vA1, h2A[j]);
            UNPACK2(vB0, vB1, h2B[j]);
            float w30 = cW3[2 * j], w31 = cW3[2 * j + 1];
            logitA = fmaf(fmaxf(vA0, 0.01f * vA0), w30, logitA);
            logitA = fmaf(fmaxf(vA1, 0.01f * vA1), w31, logitA);
            logitB = fmaf(fmaxf(vB0, 0.01f * vB0), w30, logitB);
            logitB = fmaf(fmaxf(vB1, 0.01f * vB1), w31, logitB);
        }

        sL[k * 64 + pA] = validA ? logitA : -100.0f;
        sL[k * 64 + pB] = validB ? logitB : -100.0f;
    }
    __syncthreads();

    // ---- phase 4: softmax over 9 dirs, write out ----
    if (tid < 64) {
        float v[9], m = -1e30f;
#pragma unroll
        for (int k = 0; k < 9; k++) {
            v[k] = sL[k * 64 + tid];
            m = fmaxf(m, v[k]);
        }
        float s = 0.f;
#pragma unroll
        for (int k = 0; k < 9; k++) {
            v[k] = __expf(v[k] - m);
            s += v[k];
        }
        float inv = 1.f / s;
        float* op = out + (((size_t)b * 9) * H + y) * W + x0 + tid;
#pragma unroll
        for (int k = 0; k < 9; k++)
            op[(size_t)k * H * W] = v[k] * inv;
    }
}

// ---------------------------------------------------------------------------
extern "C" void kernel_launch(void* const* d_in, const int* in_sizes, int n_in,
                              void* d_out, int out_size)
{
    const float* lr = (const float*)d_in[0];
    const float* hr = (const float*)d_in[1];
    // d_in[2], d_in[3] (lr_feature_r / hr_feature_r) unused by the reference
    const float* w0 = (const float*)d_in[4];
    const float* w1 = (const float*)d_in[5];
    const float* w2 = (const float*)d_in[6];
    const float* w3 = (const float*)d_in[7];
    float* out = (float*)d_out;

    // transpose weights into staging, then D2D-copy into constant memory
    k_prep_w<<<1, 512>>>(w1, w2);
    void* w1t_ptr = nullptr; void* w2t_ptr = nullptr;
    cudaGetSymbolAddress(&w1t_ptr, g_W1t);
    cudaGetSymbolAddress(&w2t_ptr, g_W2t);
    cudaMemcpyToSymbolAsync(cW1, w1t_ptr, 32 * 16 * sizeof(float), 0,
                            cudaMemcpyDeviceToDevice, 0);
    cudaMemcpyToSymbolAsync(cW2, w2t_ptr, 16 * 8 * sizeof(float), 0,
                            cudaMemcpyDeviceToDevice, 0);
    cudaMemcpyToSymbolAsync(cW3, w3, 8 * sizeof(float), 0,
                            cudaMemcpyDeviceToDevice, 0);

    k_precompute_P<<<(Bn * LH * LW * 4 + 255) / 256, 256>>>(lr, w0);

    dim3 grid(W / 64, H, Bn);
    k_main<<<grid, 288>>>(hr, w0, out);
}

// round 12
// speedup vs baseline: 2.1900x; 1.1595x over previous
#include <cuda_runtime.h>
#include <math.h>

#define Bn 2
#define C 32
#define H 256
#define W 512
#define LH 64
#define LW 128
#define N_HP (Bn * H * W)      // 262144 hr pixels
#define N_P  (Bn * LH * LW)    // 16384 lr pixels

#define STR 36   // activation row stride (floats): 144B, 16B-aligned, bank-rotating

// packed f32x2 helpers (Blackwell sm_103a)
#define FMA2(d, a, b, c) \
    asm("fma.rn.f32x2 %0, %1, %2, %3;" : "=l"(d) : "l"(a), "l"(b), "l"(c))
#define PACK2(d, lo, hi) \
    asm("mov.b64 %0, {%1, %2;};" : "=l"(d) : "f"(lo), "f"(hi))
#undef PACK2
#define PACK2(d, lo, hi) \
    asm("mov.b64 %0, {%1, %2};" : "=l"(d) : "f"(lo), "f"(hi))
#define UNPACK2(lo, hi, s) \
    asm("mov.b64 {%0, %1}, %2;" : "=f"(lo), "=f"(hi) : "l"(s))

// Constant-memory weights (all [c][o] / [c][j] layouts)
__constant__ float cW0hr[32 * 32];
__constant__ float cW0lr[32 * 32];
__constant__ float cW1[32 * 16];
__constant__ float cW2[16 * 8];
__constant__ float cW3[8];

// staging for memcpyToSymbol + scratch tables
__device__ float g_W0hrt[32 * 32];
__device__ float g_W0lrt[32 * 32];
__device__ float g_W1t[32 * 16];
__device__ float g_W2t[16 * 8];
__device__ float g_DT[9 * 16 * 32];           // dt[k][py*4+px][o]
__device__ float g_P[N_P * 32];               // W0_lr @ lr  per lr pixel
__device__ float g_HP[(size_t)N_HP * 32];     // W0_hr @ hr  per hr pixel (32 MB)

// ---------------------------------------------------------------------------
// Prep: transpose weights into [c][*] staging, build full dt table.
// ---------------------------------------------------------------------------
__global__ void k_prep(const float* __restrict__ w0,
                       const float* __restrict__ w1,
                       const float* __restrict__ w2)
{
    int t = threadIdx.x;
    for (int i = t; i < 1024; i += 512) {
        int c = i >> 5, o = i & 31;
        g_W0hrt[i] = w0[o * 66 + 32 + c];
        g_W0lrt[i] = w0[o * 66 + c];
    }
    if (t < 512) { int c = t >> 4, j = t & 15; g_W1t[c * 16 + j] = w1[j * 32 + c]; }
    if (t < 128) { int c = t >> 3, j = t & 7;  g_W2t[c * 8 + j]  = w2[j * 16 + c]; }

    for (int i = t; i < 9 * 16 * 32; i += 512) {
        int o  = i & 31;
        int px = (i >> 5) & 3;
        int py = (i >> 7) & 3;
        int k  = i >> 9;
        float bxf = (px < 2) ? (float)(px - 2) : (float)(px - 1);
        float byf = (py < 2) ? (float)(py - 2) : (float)(py - 1);
        float d0, d1;
        if (k == 0)                { d0 = bxf;              d1 = byf;              }
        else if (k == 1 || k == 5) { d0 = 4.f - (float)px;  d1 = byf;              }
        else if (k == 2 || k == 6) { d0 = (float)px + 1.f;  d1 = byf;              }
        else if (k == 3 || k == 7) { d0 = bxf;              d1 = 4.f - (float)py;  }
        else                       { d0 = bxf;              d1 = (float)py + 1.f;  }
        g_DT[i] = w0[o * 66 + 64] * d0 + w0[o * 66 + 65] * d1;
    }
}

// ---------------------------------------------------------------------------
// Projection: g_HP[i][o] = W0_hr @ hr(pixel i);  g_P[j][o] = W0_lr @ lr(pixel j)
// One thread per pixel, 32 outputs as 16 packed f32x2 accumulators.
// ---------------------------------------------------------------------------
__global__ __launch_bounds__(256) void k_proj(
    const float* __restrict__ hr, const float* __restrict__ lr)
{
    int i = blockIdx.x * 256 + threadIdx.x;
    unsigned long long acc[16];
#pragma unroll
    for (int q = 0; q < 16; q++) acc[q] = 0ULL;

    if (i < N_HP) {
        int b   = i / (H * W);
        int rem = i - b * (H * W);
        const float* src = hr + (size_t)b * C * H * W + rem;
#pragma unroll 4
        for (int c = 0; c < 32; c++) {
            float v = src[(size_t)c * H * W];
            unsigned long long vv;
            PACK2(vv, v, v);
            const ulonglong2* wp = (const ulonglong2*)&cW0hr[c * 32];
#pragma unroll
            for (int q = 0; q < 8; q++) {
                ulonglong2 wv = wp[q];
                FMA2(acc[q * 2 + 0], vv, wv.x, acc[q * 2 + 0]);
                FMA2(acc[q * 2 + 1], vv, wv.y, acc[q * 2 + 1]);
            }
        }
        ulonglong2* dst = (ulonglong2*)&g_HP[(size_t)i * 32];
#pragma unroll
        for (int q = 0; q < 8; q++)
            dst[q] = make_ulonglong2(acc[q * 2], acc[q * 2 + 1]);
    } else {
        int j = i - N_HP;
        if (j >= N_P) return;
        int b   = j / (LH * LW);
        int rem = j - b * (LH * LW);
        const float* src = lr + (size_t)b * C * LH * LW + rem;
#pragma unroll 4
        for (int c = 0; c < 32; c++) {
            float v = src[c * (LH * LW)];
            unsigned long long vv;
            PACK2(vv, v, v);
            const ulonglong2* wp = (const ulonglong2*)&cW0lr[c * 32];
#pragma unroll
            for (int q = 0; q < 8; q++) {
                ulonglong2 wv = wp[q];
                FMA2(acc[q * 2 + 0], vv, wv.x, acc[q * 2 + 0]);
                FMA2(acc[q * 2 + 1], vv, wv.y, acc[q * 2 + 1]);
            }
        }
        ulonglong2* dst = (ulonglong2*)&g_P[(size_t)j * 32];
#pragma unroll
        for (int q = 0; q < 8; q++)
            dst[q] = make_ulonglong2(acc[q * 2], acc[q * 2 + 1]);
    }
}

// ---------------------------------------------------------------------------
// Main kernel. Block = 64-pixel strip (one row) x 9 directions.
// 288 threads = 9 warps; warp k = direction k; lane handles pixels lane,
// lane+32. Prologue is 3 float4 copy loops + ONE sync; weights from const.
// ---------------------------------------------------------------------------
__global__ __launch_bounds__(288, 3) void k_main(float* __restrict__ out)
{
    __shared__ __align__(16) float sHP[64 * STR];    // hpart [pix][o]
    __shared__ __align__(16) float sP[54 * STR];     // P halo [3x18 cells][o]
    __shared__ __align__(16) float sDT[36 * STR];    // dt [k*4+px][o]
    __shared__ float sL[9 * 64];                     // logits [k][pix]

    const int tid = threadIdx.x;
    const int x0  = blockIdx.x * 64;
    const int y   = blockIdx.y;
    const int b   = blockIdx.z;
    const int py  = y & 3;
    const int ly0 = y >> 2;
    const int lx0 = x0 >> 2;

    // ---- prologue: three copy loops, one sync ----
    {
        const float* hp_src = g_HP + (((size_t)b * H + y) * W + x0) * 32;
        for (int i = tid; i < 512; i += 288) {
            int pix = i >> 3;
            int og  = (i & 7) << 2;
            *(float4*)&sHP[pix * STR + og] = *(const float4*)&hp_src[pix * 32 + og];
        }
        for (int i = tid; i < 54 * 8; i += 288) {
            int cell = i >> 3;
            int og   = (i & 7) << 2;
            int lxl  = cell % 18, lyl = cell / 18;
            int glx  = min(max(lx0 - 1 + lxl, 0), LW - 1);
            int gly  = min(max(ly0 - 1 + lyl, 0), LH - 1);
            *(float4*)&sP[cell * STR + og] =
                *(const float4*)&g_P[(((size_t)b * LH + gly) * LW + glx) * 32 + og];
        }
        for (int i = tid; i < 9 * 4 * 8; i += 288) {
            int og = (i & 7) << 2;
            int px = (i >> 3) & 3;
            int kk = i >> 5;
            *(float4*)&sDT[(kk * 4 + px) * STR + og] =
                *(const float4*)&g_DT[((kk * 16 + py * 4 + px) << 5) + og];
        }
    }
    __syncthreads();

    // ---- MLP: warp k = direction k; lane does pixels lane, lane+32 ----
    {
        const int k    = tid >> 5;          // 0..8
        const int lane = tid & 31;
        const int pA   = lane;
        const int pB   = lane + 32;
        const int px   = pA & 3;

        // dir offsets: dy=-1 k in {3,5,6}, dy=+1 {4,7,8}; dx=-1 {1,5,7}, dx=+1 {2,6,8}
        const unsigned NY = (1u<<3)|(1u<<5)|(1u<<6), PY = (1u<<4)|(1u<<7)|(1u<<8);
        const unsigned NX = (1u<<1)|(1u<<5)|(1u<<7), PX = (1u<<2)|(1u<<6)|(1u<<8);
        int dy = (int)((PY >> k) & 1u) - (int)((NY >> k) & 1u);
        int dx = (int)((PX >> k) & 1u) - (int)((NX >> k) & 1u);
        int yn = y + dy * 4;
        bool vy = (yn >= 0) & (yn < H);
        int xnA = x0 + pA + dx * 4;
        int xnB = x0 + pB + dx * 4;
        bool validA = vy & (xnA >= 0) & (xnA < W);
        bool validB = vy & (xnB >= 0) & (xnB < W);

        const float* hpA = &sHP[pA * STR];
        const float* hpB = &sHP[pB * STR];
        const float* prA = &sP[((1 + dy) * 18 + (pA >> 2) + 1 + dx) * STR];
        const float* prB = prA + 8 * STR;
        const float* dtr = &sDT[(k * 4 + px) * STR];

        unsigned long long h1A[8], h1B[8];
#pragma unroll
        for (int j = 0; j < 8; j++) { h1A[j] = 0ULL; h1B[j] = 0ULL; }

#pragma unroll 2
        for (int c4 = 0; c4 < 32; c4 += 4) {
            const float4 hA4 = *(const float4*)&hpA[c4];
            const float4 hB4 = *(const float4*)&hpB[c4];
            const float4 pA4 = *(const float4*)&prA[c4];
            const float4 pB4 = *(const float4*)&prB[c4];
            const float4 dt4 = *(const float4*)&dtr[c4];

            float aA[4], aB[4];
            {
                float t;
                t = hA4.x + pA4.x + dt4.x; aA[0] = fmaxf(t, 0.01f * t);
                t = hA4.y + pA4.y + dt4.y; aA[1] = fmaxf(t, 0.01f * t);
                t = hA4.z + pA4.z + dt4.z; aA[2] = fmaxf(t, 0.01f * t);
                t = hA4.w + pA4.w + dt4.w; aA[3] = fmaxf(t, 0.01f * t);
                t = hB4.x + pB4.x + dt4.x; aB[0] = fmaxf(t, 0.01f * t);
                t = hB4.y + pB4.y + dt4.y; aB[1] = fmaxf(t, 0.01f * t);
                t = hB4.z + pB4.z + dt4.z; aB[2] = fmaxf(t, 0.01f * t);
                t = hB4.w + pB4.w + dt4.w; aB[3] = fmaxf(t, 0.01f * t);
            }
#pragma unroll
            for (int cc = 0; cc < 4; cc++) {
                const int c = c4 + cc;
                const ulonglong2* wp = (const ulonglong2*)&cW1[c * 16];
                unsigned long long apA, apB;
                PACK2(apA, aA[cc], aA[cc]);
                PACK2(apB, aB[cc], aB[cc]);
#pragma unroll
                for (int q = 0; q < 4; q++) {
                    ulonglong2 wv = wp[q];
                    FMA2(h1A[q * 2 + 0], apA, wv.x, h1A[q * 2 + 0]);
                    FMA2(h1A[q * 2 + 1], apA, wv.y, h1A[q * 2 + 1]);
                    FMA2(h1B[q * 2 + 0], apB, wv.x, h1B[q * 2 + 0]);
                    FMA2(h1B[q * 2 + 1], apB, wv.y, h1B[q * 2 + 1]);
                }
            }
        }

        unsigned long long h2A[4], h2B[4];
#pragma unroll
        for (int j = 0; j < 4; j++) { h2A[j] = 0ULL; h2B[j] = 0ULL; }
#pragma unroll 2
        for (int c2 = 0; c2 < 8; c2++) {
            float uA0, uA1, uB0, uB1;
            UNPACK2(uA0, uA1, h1A[c2]);
            UNPACK2(uB0, uB1, h1B[c2]);
            uA0 = fmaxf(uA0, 0.01f * uA0);  uA1 = fmaxf(uA1, 0.01f * uA1);
            uB0 = fmaxf(uB0, 0.01f * uB0);  uB1 = fmaxf(uB1, 0.01f * uB1);
            unsigned long long aA0, aA1, aB0, aB1;
            PACK2(aA0, uA0, uA0); PACK2(aA1, uA1, uA1);
            PACK2(aB0, uB0, uB0); PACK2(aB1, uB1, uB1);

            const ulonglong2* wp0 = (const ulonglong2*)&cW2[(2 * c2) * 8];
            const ulonglong2* wp1 = (const ulonglong2*)&cW2[(2 * c2 + 1) * 8];
            ulonglong2 w0v = wp0[0], w0w = wp0[1];
            ulonglong2 w1v = wp1[0], w1w = wp1[1];
            FMA2(h2A[0], aA0, w0v.x, h2A[0]); FMA2(h2A[1], aA0, w0v.y, h2A[1]);
            FMA2(h2A[2], aA0, w0w.x, h2A[2]); FMA2(h2A[3], aA0, w0w.y, h2A[3]);
            FMA2(h2A[0], aA1, w1v.x, h2A[0]); FMA2(h2A[1], aA1, w1v.y, h2A[1]);
            FMA2(h2A[2], aA1, w1w.x, h2A[2]); FMA2(h2A[3], aA1, w1w.y, h2A[3]);
            FMA2(h2B[0], aB0, w0v.x, h2B[0]); FMA2(h2B[1], aB0, w0v.y, h2B[1]);
            FMA2(h2B[2], aB0, w0w.x, h2B[2]); FMA2(h2B[3], aB0, w0w.y, h2B[3]);
            FMA2(h2B[0], aB1, w1v.x, h2B[0]); FMA2(h2B[1], aB1, w1v.y, h2B[1]);
            FMA2(h2B[2], aB1, w1w.x, h2B[2]); FMA2(h2B[3], aB1, w1w.y, h2B[3]);
        }

        float logitA = 0.f, logitB = 0.f;
#pragma unroll
        for (int j = 0; j < 4; j++) {
            float vA0, vA1, vB0, vB1;
            UNPACK2(vA0, vA1, h2A[j]);
            UNPACK2(vB0, vB1, h2B[j]);
            float w30 = cW3[2 * j], w31 = cW3[2 * j + 1];
            logitA = fmaf(fmaxf(vA0, 0.01f * vA0), w30, logitA);
            logitA = fmaf(fmaxf(vA1, 0.01f * vA1), w31, logitA);
            logitB = fmaf(fmaxf(vB0, 0.01f * vB0), w30, logitB);
            logitB = fmaf(fmaxf(vB1, 0.01f * vB1), w31, logitB);
        }

        sL[k * 64 + pA] = validA ? logitA : -100.0f;
        sL[k * 64 + pB] = validB ? logitB : -100.0f;
    }
    __syncthreads();

    // ---- softmax over 9 dirs, write out ----
    if (tid < 64) {
        float v[9], m = -1e30f;
#pragma unroll
        for (int k = 0; k < 9; k++) {
            v[k] = sL[k * 64 + tid];
            m = fmaxf(m, v[k]);
        }
        float s = 0.f;
#pragma unroll
        for (int k = 0; k < 9; k++) {
            v[k] = __expf(v[k] - m);
            s += v[k];
        }
        float inv = 1.f / s;
        float* op = out + (((size_t)b * 9) * H + y) * W + x0 + tid;
#pragma unroll
        for (int k = 0; k < 9; k++)
            op[(size_t)k * H * W] = v[k] * inv;
    }
}

// ---------------------------------------------------------------------------
extern "C" void kernel_launch(void* const* d_in, const int* in_sizes, int n_in,
                              void* d_out, int out_size)
{
    const float* lr = (const float*)d_in[0];
    const float* hr = (const float*)d_in[1];
    // d_in[2], d_in[3] (lr_feature_r / hr_feature_r) unused by the reference
    const float* w0 = (const float*)d_in[4];
    const float* w1 = (const float*)d_in[5];
    const float* w2 = (const float*)d_in[6];
    const float* w3 = (const float*)d_in[7];
    float* out = (float*)d_out;

    k_prep<<<1, 512>>>(w0, w1, w2);

    void *p0, *p1, *p2, *p3;
    cudaGetSymbolAddress(&p0, g_W0hrt);
    cudaGetSymbolAddress(&p1, g_W0lrt);
    cudaGetSymbolAddress(&p2, g_W1t);
    cudaGetSymbolAddress(&p3, g_W2t);
    cudaMemcpyToSymbolAsync(cW0hr, p0, 1024 * sizeof(float), 0,
                            cudaMemcpyDeviceToDevice, 0);
    cudaMemcpyToSymbolAsync(cW0lr, p1, 1024 * sizeof(float), 0,
                            cudaMemcpyDeviceToDevice, 0);
    cudaMemcpyToSymbolAsync(cW1, p2, 512 * sizeof(float), 0,
                            cudaMemcpyDeviceToDevice, 0);
    cudaMemcpyToSymbolAsync(cW2, p3, 128 * sizeof(float), 0,
                            cudaMemcpyDeviceToDevice, 0);
    cudaMemcpyToSymbolAsync(cW3, w3, 8 * sizeof(float), 0,
                            cudaMemcpyDeviceToDevice, 0);

    k_proj<<<(N_HP + N_P + 255) / 256, 256>>>(hr, lr);

    dim3 grid(W / 64, H, Bn);
    k_main<<<grid, 288>>>(out);
}